// round 11
// baseline (speedup 1.0000x reference)
#include <cuda_runtime.h>
#include <cuda_fp16.h>
#include <cstdint>

// Problem constants
#define BATCH 128
#define SEQT  512
#define DIN   1024
#define HID   128
#define GATES 512
#define NCLS  8
#define MTOT  (BATCH * SEQT)      // 65536
#define MTILES (MTOT / 128)       // 512
#define NCH0  48                  // 3*1024/64 k-chunks, layer 0
#define NCH1  6                   // 3*128/64  k-chunks, layer 1

// ---------------- scratch (device globals; no allocation) ----------------
__device__ __align__(1024) __half g_as[(size_t)MTILES * NCH0 * 8192];  // 384MB split-fp16 A tiles
__device__ __align__(1024) __half g_bs0[(size_t)NCH0 * 32768];         // 3MB  split-fp16 W_ih0
__device__ __align__(1024) __half g_bs1[(size_t)NCH1 * 32768];         // 384KB split-fp16 W_ih1
__device__ float g_xg[(size_t)MTOT * GATES];   // 128MB gate pre-activations
__device__ float g_h1[(size_t)MTOT * HID];     // 32MB layer-0 hidden states
__device__ float g_hlast[BATCH * HID];

// ---------------- PTX helpers (all sm_103 baseline; NO tcgen05) ----------------
__device__ __forceinline__ uint32_t smem_u32(const void* p) {
    uint32_t a;
    asm("{ .reg .u64 t; cvta.to.shared.u64 t, %1; cvt.u32.u64 %0, t; }" : "=r"(a) : "l"(p));
    return a;
}
__device__ __forceinline__ void mbar_init(uint32_t m, uint32_t cnt) {
    asm volatile("mbarrier.init.shared.b64 [%0], %1;" :: "r"(m), "r"(cnt) : "memory");
}
__device__ __forceinline__ void mbar_expect_tx(uint32_t m, uint32_t b) {
    asm volatile("mbarrier.arrive.expect_tx.shared.b64 _, [%0], %1;" :: "r"(m), "r"(b) : "memory");
}
__device__ __forceinline__ void mbar_wait(uint32_t m, uint32_t ph) {
    asm volatile(
        "{\n\t.reg .pred P;\n\t"
        "WL_%=:\n\t"
        "mbarrier.try_wait.parity.shared.b64 P, [%0], %1;\n\t"
        "@P bra WD_%=;\n\t"
        "bra WL_%=;\n\t"
        "WD_%=:\n\t}"
        :: "r"(m), "r"(ph) : "memory");
}
__device__ __forceinline__ void bulk_g2s(uint32_t dst, const void* src, uint32_t bytes, uint32_t mbar) {
    asm volatile(
        "cp.async.bulk.shared::cluster.global.mbarrier::complete_tx::bytes [%0], [%1], %2, [%3];"
        :: "r"(dst), "l"(src), "r"(bytes), "r"(mbar) : "memory");
}
__device__ __forceinline__ void ldsm_x4(uint32_t& r0, uint32_t& r1, uint32_t& r2, uint32_t& r3,
                                        uint32_t a) {
    asm volatile("ldmatrix.sync.aligned.m8n8.x4.shared.b16 {%0,%1,%2,%3}, [%4];"
        : "=r"(r0), "=r"(r1), "=r"(r2), "=r"(r3) : "r"(a));
}
__device__ __forceinline__ void mma16816(float& d0, float& d1, float& d2, float& d3,
                                         uint32_t a0, uint32_t a1, uint32_t a2, uint32_t a3,
                                         uint32_t b0, uint32_t b1) {
    asm volatile("mma.sync.aligned.m16n8k16.row.col.f32.f16.f16.f32 "
        "{%0,%1,%2,%3},{%4,%5,%6,%7},{%8,%9},{%0,%1,%2,%3};"
        : "+f"(d0), "+f"(d1), "+f"(d2), "+f"(d3)
        : "r"(a0), "r"(a1), "r"(a2), "r"(a3), "r"(b0), "r"(b1));
}

// ---- packed f32x2 FMA (Blackwell FFMA2) ----
typedef unsigned long long u64b;
__device__ __forceinline__ void ffma2(u64b& d, u64b a, u64b b) {
    asm("fma.rn.f32x2 %0, %1, %2, %0;" : "+l"(d) : "l"(a), "l"(b));
}
__device__ __forceinline__ u64b pk64(float x, float y) {
    u64b r; asm("mov.b64 %0, {%1, %2};" : "=l"(r) : "f"(x), "f"(y)); return r;
}
__device__ __forceinline__ float2 upk64(u64b v) {
    float2 r; asm("mov.b64 {%0, %1}, %2;" : "=f"(r.x), "=f"(r.y) : "l"(v)); return r;
}

// ---------------- split-fp16 packing ----------------
__device__ __forceinline__ uint32_t pk2(float f0, float f1, bool lo) {
    __half h0 = __float2half_rn(f0);
    __half h1 = __float2half_rn(f1);
    if (lo) {
        h0 = __float2half_rn(f0 - __half2float(h0));
        h1 = __float2half_rn(f1 - __half2float(h1));
    }
    __half2 p = __halves2half2(h0, h1);
    return *reinterpret_cast<uint32_t*>(&p);
}

// ---------------- conversion: activations -> tiled+swizzled split-fp16 ----------------
// A' layout: [mt][chunk][128 rows x 64 fp16, SW128] (16KB tiles)
// slabs along logical K' = 3K: [hi | hi | lo]
__global__ void conv_a_kernel(const float* __restrict__ src, __half* __restrict__ dst,
                              int nchunk, int kshift)
{
    int idx = blockIdx.x * 256 + threadIdx.x;
    int u  = idx & 1023;
    int t2 = idx >> 10;
    int c  = t2 % nchunk;
    int mt = t2 / nchunk;
    int r = u >> 3, g = u & 7;
    int kk = c * 64 + g * 8;
    int slab = kk >> kshift;
    int k = kk - (slab << kshift);
    const float* xr = src + (((size_t)(mt * 128 + r)) << kshift) + k;
    float4 v0 = *(const float4*)xr;
    float4 v1 = *(const float4*)(xr + 4);
    bool lo = (slab == 2);
    uint4 o;
    o.x = pk2(v0.x, v0.y, lo);
    o.y = pk2(v0.z, v0.w, lo);
    o.z = pk2(v1.x, v1.y, lo);
    o.w = pk2(v1.z, v1.w, lo);
    uint32_t ob = (uint32_t)((r << 7) | (g << 4));
    uint32_t so = ob ^ ((ob >> 3) & 0x70);
    char* tile = (char*)(dst + (((size_t)(mt * nchunk + c)) << 13));
    *(uint4*)(tile + so) = o;
}

// weights -> [chunk][512 rows x 64 fp16, SW128-swizzled] (64KB chunks)
// slabs along K': [hi | lo | hi]  (pairs with A's [hi | hi | lo])
__global__ void conv_b_kernel(const float* __restrict__ w, __half* __restrict__ dst,
                              int kshift)
{
    int idx = blockIdx.x * 256 + threadIdx.x;
    int g = idx & 7;
    int n = (idx >> 3) & 511;
    int c = idx >> 12;
    int kk = c * 64 + g * 8;
    int slab = kk >> kshift;
    int k = kk - (slab << kshift);
    const float* wr = w + (((size_t)n) << kshift) + k;
    float4 v0 = *(const float4*)wr;
    float4 v1 = *(const float4*)(wr + 4);
    bool lo = (slab == 1);
    uint4 o;
    o.x = pk2(v0.x, v0.y, lo);
    o.y = pk2(v0.z, v0.w, lo);
    o.z = pk2(v1.x, v1.y, lo);
    o.w = pk2(v1.z, v1.w, lo);
    uint32_t ob = (uint32_t)((n << 7) | (g << 4));
    uint32_t so = ob ^ ((ob >> 3) & 0x70);
    char* chunk = (char*)(dst + (((size_t)c) << 15));
    *(uint4*)(chunk + so) = o;
}

// ---------------- HMMA GEMM: C[128 rows x 256 gates] per CTA (proven 428us, untouched) ----------------
#define GEMM_SMEM 152576
__global__ __launch_bounds__(512, 1) void gemm_hmma_kernel(
    const __half* __restrict__ Ap, const __half* __restrict__ Bp,
    const float* __restrict__ b1, const float* __restrict__ b2,
    float* __restrict__ C, int nchunk)
{
    extern __shared__ char smem_raw[];
    uint32_t sb0 = smem_u32(smem_raw);
    uint32_t ab = (sb0 + 1023) & ~1023u;                 // 1024-aligned base
    float* smbias = (float*)(smem_raw + (ab - sb0));     // 512 floats at offset 0

    const int tid = threadIdx.x;
    const int lane = tid & 31, wid = tid >> 5;
    const int wm = wid >> 2, wn = wid & 3;
    const int sub = lane >> 3, l7 = lane & 7;

    if (tid < 512) smbias[tid] = b1[tid] + b2[tid];
    if (tid == 0) {
        mbar_init(ab + 2048, 1); mbar_init(ab + 2056, 1); mbar_init(ab + 2064, 1);
    }
    __syncthreads();

    const int mt = blockIdx.x >> 1, j = blockIdx.x & 1;
    const char* Asrc = (const char*)Ap + ((size_t)mt * nchunk) * 16384;
    const char* Bsrc = (const char*)Bp + (size_t)j * 32768;

    if (tid == 0) {
        int npre = nchunk < 3 ? nchunk : 3;
        for (int c = 0; c < npre; c++) {
            uint32_t st = ab + 4096 + c * 49152;
            uint32_t mb = ab + 2048 + c * 8;
            mbar_expect_tx(mb, 49152);
            bulk_g2s(st,         Asrc + (size_t)c * 16384, 16384, mb);
            bulk_g2s(st + 16384, Bsrc + (size_t)c * 65536, 32768, mb);
        }
    }

    float acc[2][8][4];
#pragma unroll
    for (int a = 0; a < 2; a++)
#pragma unroll
        for (int b = 0; b < 8; b++)
#pragma unroll
            for (int d = 0; d < 4; d++) acc[a][b][d] = 0.0f;

    const uint32_t xorv = (uint32_t)(l7 << 4);
    const uint32_t arow = (uint32_t)((wm * 32 + (sub & 1) * 8 + l7) * 128);
    const uint32_t akh  = (uint32_t)((sub >> 1) * 16);
    const uint32_t brow = (uint32_t)((wn * 64 + (sub >> 1) * 8 + l7) * 128);
    const uint32_t bkh  = (uint32_t)((sub & 1) * 16);

    for (int c = 0; c < nchunk; c++) {
        int s = c % 3;
        uint32_t ph = (uint32_t)((c / 3) & 1);
        uint32_t mb_full = ab + 2048 + s * 8;
        mbar_wait(mb_full, ph);
        uint32_t Abase = ab + 4096 + s * 49152;
        uint32_t Bbase = Abase + 16384;

#pragma unroll
        for (int ks = 0; ks < 4; ks++) {
            uint32_t ak = ((uint32_t)(ks * 32) + akh) ^ xorv;
            uint32_t bk = ((uint32_t)(ks * 32) + bkh) ^ xorv;
            uint32_t a0[4], a1[4], bf[4][4];
            ldsm_x4(a0[0], a0[1], a0[2], a0[3], Abase + arow + ak);
            ldsm_x4(a1[0], a1[1], a1[2], a1[3], Abase + arow + 2048 + ak);
#pragma unroll
            for (int nb2 = 0; nb2 < 4; nb2++)
                ldsm_x4(bf[nb2][0], bf[nb2][1], bf[nb2][2], bf[nb2][3],
                        Bbase + brow + nb2 * 2048 + bk);
#pragma unroll
            for (int nb = 0; nb < 8; nb++) {
                uint32_t bb0 = bf[nb >> 1][(nb & 1) * 2];
                uint32_t bb1 = bf[nb >> 1][(nb & 1) * 2 + 1];
                mma16816(acc[0][nb][0], acc[0][nb][1], acc[0][nb][2], acc[0][nb][3],
                         a0[0], a0[1], a0[2], a0[3], bb0, bb1);
                mma16816(acc[1][nb][0], acc[1][nb][1], acc[1][nb][2], acc[1][nb][3],
                         a1[0], a1[1], a1[2], a1[3], bb0, bb1);
            }
        }
        __syncthreads();
        if (tid == 0 && c + 3 < nchunk) {
            uint32_t st = ab + 4096 + s * 49152;
            mbar_expect_tx(mb_full, 49152);
            bulk_g2s(st,         Asrc + (size_t)(c + 3) * 16384, 16384, mb_full);
            bulk_g2s(st + 16384, Bsrc + (size_t)(c + 3) * 65536, 32768, mb_full);
        }
    }

    const int mbase = mt * 128 + wm * 32 + (lane >> 2);
    const int colb  = j * 256 + wn * 64 + (lane & 3) * 2;
#pragma unroll
    for (int mb = 0; mb < 2; mb++)
#pragma unroll
        for (int nb = 0; nb < 8; nb++) {
            int cc = colb + nb * 8;
            float bx = smbias[cc], by = smbias[cc + 1];
            size_t r0 = (size_t)(mbase + mb * 16) * GATES + cc;
            float2 v0 = make_float2(acc[mb][nb][0] + bx, acc[mb][nb][1] + by);
            float2 v1 = make_float2(acc[mb][nb][2] + bx, acc[mb][nb][3] + by);
            *(float2*)(C + r0) = v0;
            *(float2*)(C + r0 + (size_t)8 * GATES) = v1;
        }
}

// ---------------- activations ----------------
__device__ __forceinline__ float sigmoidf_(float x) {
    return __fdividef(1.0f, 1.0f + __expf(-x));
}
__device__ __forceinline__ float tanhf_(float x) {
    float a = __expf(2.0f * fabsf(x));
    float r = 1.0f - __fdividef(2.0f, 1.0f + a);
    return copysignf(r, x);
}

// ---------------- LSTM recurrence: 256 threads, 2 gates/thread, 104/24 reg split ----------------
// Thread tid owns gate rows tid and tid+256.
// Per gate: k 0..103 in regs (52 u64b, loaded directly as raw fp32 pairs),
//           k 104..127 from smem (6 float4).
// Weight regs = 208; total ~240 < 255-reg cap at 256 thr.
// LDS per step: weights 384 wf + h-broadcast 256 wf  (vs 512+256 in R10).
#define REC_SMEM (6 * 512 * 16 + 128 * 4 + 512 * 4)
__global__ __launch_bounds__(256, 1) void lstm_rec_kernel(
    const float* __restrict__ xg, const float* __restrict__ w_hh,
    float* __restrict__ hout, float* __restrict__ hlast, int T)
{
    extern __shared__ float smem[];
    float4* sw = (float4*)smem;                 // [kc 0..5][row 0..511] float4 (k=104..127)
    float* h_s = smem + 6 * 512 * 4;            // 128 floats
    float* gates = h_s + 128;                   // 512 floats (activated)

    const int tid = threadIdx.x;
    const int b = blockIdx.x;
    const int rowA = tid;                        // i (0..127) / f (128..255): sigmoid
    const int rowB = tid + 256;                  // g (256..383): tanh / o (384..511): sigmoid
    const bool b_is_tanh = (tid < 128);

    // raw fp32 pairs ARE the packed f32x2 operands — load directly as u64
    const u64b* wrowA = (const u64b*)(w_hh + (size_t)rowA * HID);
    const u64b* wrowB = (const u64b*)(w_hh + (size_t)rowB * HID);
    u64b wrA[52], wrB[52];
#pragma unroll
    for (int i = 0; i < 52; i++) {
        wrA[i] = wrowA[i];                      // k = 2i, 2i+1
        wrB[i] = wrowB[i];
    }
    const float4* wrowA4 = (const float4*)wrowA;
    const float4* wrowB4 = (const float4*)wrowB;
#pragma unroll
    for (int kc = 0; kc < 6; kc++) {
        sw[kc * 512 + rowA] = wrowA4[26 + kc];  // k = 104..127
        sw[kc * 512 + rowB] = wrowB4[26 + kc];
    }

    if (tid < HID) h_s[tid] = 0.0f;
    float c = 0.0f;
    __syncthreads();

    const float* xg_bA = xg + ((size_t)b * T) * GATES + rowA;
    const float* xg_bB = xg + ((size_t)b * T) * GATES + rowB;
    float xgA = xg_bA[0];
    float xgB = xg_bB[0];

    for (int t = 0; t < T; t++) {
        float xgA_n = (t + 1 < T) ? xg_bA[(size_t)(t + 1) * GATES] : 0.0f;
        float xgB_n = (t + 1 < T) ? xg_bB[(size_t)(t + 1) * GATES] : 0.0f;

        u64b a0 = pk64(xgA, 0.0f), a1 = pk64(0.0f, 0.0f);
        u64b b0 = pk64(xgB, 0.0f), b1 = pk64(0.0f, 0.0f);
        const ulonglong2* h2 = (const ulonglong2*)h_s;
        // k = 0..103: h broadcast + register weights, 4 independent chains
#pragma unroll
        for (int i = 0; i < 26; i++) {
            ulonglong2 hv = h2[i];
            ffma2(a0, hv.x, wrA[2 * i]);
            ffma2(a1, hv.y, wrA[2 * i + 1]);
            ffma2(b0, hv.x, wrB[2 * i]);
            ffma2(b1, hv.y, wrB[2 * i + 1]);
        }
        // k = 104..127: weights from smem
#pragma unroll
        for (int kc = 0; kc < 6; kc++) {
            ulonglong2 hv = h2[26 + kc];
            float4 wa = sw[kc * 512 + rowA];
            ulonglong2 wau = *reinterpret_cast<ulonglong2*>(&wa);
            ffma2(a0, hv.x, wau.x);
            ffma2(a1, hv.y, wau.y);
            float4 wb = sw[kc * 512 + rowB];
            ulonglong2 wbu = *reinterpret_cast<ulonglong2*>(&wb);
            ffma2(b0, hv.x, wbu.x);
            ffma2(b1, hv.y, wbu.y);
        }
        float2 fa0 = upk64(a0), fa1 = upk64(a1);
        float2 fb0 = upk64(b0), fb1 = upk64(b1);
        float preA = (fa0.x + fa0.y) + (fa1.x + fa1.y);
        float preB = (fb0.x + fb0.y) + (fb1.x + fb1.y);
        gates[rowA] = sigmoidf_(preA);                                // i or f
        gates[rowB] = b_is_tanh ? tanhf_(preB) : sigmoidf_(preB);     // g or o
        __syncthreads();

        if (tid < HID) {
            float ig = gates[tid];
            float fg = gates[HID + tid];
            float gg = gates[2 * HID + tid];
            float og = gates[3 * HID + tid];
            c = fg * c + ig * gg;
            float h = og * tanhf_(c);
            h_s[tid] = h;
            if (hout) hout[((size_t)b * T + t) * HID + tid] = h;
        }
        __syncthreads();
        xgA = xgA_n;
        xgB = xgB_n;
    }
    if (hlast && tid < HID) hlast[b * HID + tid] = h_s[tid];
}

// ---------------- final FC ----------------
__global__ void fc_kernel(const float* __restrict__ hlast, const float* __restrict__ fc_w,
                          const float* __restrict__ fc_b, float* __restrict__ out)
{
    int tid = threadIdx.x;
    int b = tid >> 3;
    int cls = tid & 7;
    const float* hv = hlast + b * HID;
    const float* wv = fc_w + cls * HID;
    float s = fc_b[cls];
#pragma unroll 8
    for (int j = 0; j < HID; j++) s += hv[j] * wv[j];
    out[b * NCLS + cls] = s;
}

// ---------------- launch ----------------
extern "C" void kernel_launch(void* const* d_in, const int* in_sizes, int n_in,
                              void* d_out, int out_size)
{
    const float* x     = (const float*)d_in[0];
    const float* w_ih0 = (const float*)d_in[1];
    const float* w_hh0 = (const float*)d_in[2];
    const float* b_ih0 = (const float*)d_in[3];
    const float* b_hh0 = (const float*)d_in[4];
    const float* w_ih1 = (const float*)d_in[5];
    const float* w_hh1 = (const float*)d_in[6];
    const float* b_ih1 = (const float*)d_in[7];
    const float* b_hh1 = (const float*)d_in[8];
    const float* fc_w  = (const float*)d_in[9];
    const float* fc_b  = (const float*)d_in[10];
    float* out = (float*)d_out;

    float *xg_p = nullptr, *h1_p = nullptr, *hl_p = nullptr;
    __half *as_p = nullptr, *bs0_p = nullptr, *bs1_p = nullptr;
    cudaGetSymbolAddress((void**)&xg_p, g_xg);
    cudaGetSymbolAddress((void**)&h1_p, g_h1);
    cudaGetSymbolAddress((void**)&hl_p, g_hlast);
    cudaGetSymbolAddress((void**)&as_p, g_as);
    cudaGetSymbolAddress((void**)&bs0_p, g_bs0);
    cudaGetSymbolAddress((void**)&bs1_p, g_bs1);

    cudaFuncSetAttribute(lstm_rec_kernel,
                         cudaFuncAttributeMaxDynamicSharedMemorySize, REC_SMEM);
    cudaFuncSetAttribute(gemm_hmma_kernel,
                         cudaFuncAttributeMaxDynamicSharedMemorySize, GEMM_SMEM);

    // weight conversions (tiny)
    conv_b_kernel<<<NCH0 * 512 * 8 / 256, 256>>>(w_ih0, bs0_p, 10);
    conv_b_kernel<<<NCH1 * 512 * 8 / 256, 256>>>(w_ih1, bs1_p, 7);

    // layer 0: x -> split-fp16 tiles -> HMMA GEMM -> recurrence
    conv_a_kernel<<<MTILES * NCH0 * 1024 / 256, 256>>>(x, as_p, NCH0, 10);
    gemm_hmma_kernel<<<MTILES * 2, 512, GEMM_SMEM>>>(as_p, bs0_p, b_ih0, b_hh0, xg_p, NCH0);
    lstm_rec_kernel<<<BATCH, 256, REC_SMEM>>>(xg_p, w_hh0, h1_p, nullptr, SEQT);

    // layer 1: h1 -> split-fp16 tiles -> HMMA GEMM -> recurrence
    conv_a_kernel<<<MTILES * NCH1 * 1024 / 256, 256>>>(h1_p, as_p, NCH1, 7);
    gemm_hmma_kernel<<<MTILES * 2, 512, GEMM_SMEM>>>(as_p, bs1_p, b_ih1, b_hh1, xg_p, NCH1);
    lstm_rec_kernel<<<BATCH, 256, REC_SMEM>>>(xg_p, w_hh1, nullptr, hl_p, SEQT);

    // FC head
    fc_kernel<<<1, BATCH * NCLS>>>(hl_p, fc_w, fc_b, out);
}

// round 12
// speedup vs baseline: 1.0266x; 1.0266x over previous
#include <cuda_runtime.h>
#include <cuda_fp16.h>
#include <cstdint>

// Problem constants
#define BATCH 128
#define SEQT  512
#define DIN   1024
#define HID   128
#define GATES 512
#define NCLS  8
#define MTOT  (BATCH * SEQT)      // 65536
#define MTILES (MTOT / 128)       // 512
#define NCH0  48                  // 3*1024/64 k-chunks, layer 0
#define NCH1  6                   // 3*128/64  k-chunks, layer 1

// ---------------- scratch (device globals; no allocation) ----------------
__device__ __align__(1024) __half g_as[(size_t)MTILES * NCH0 * 8192];  // 384MB split-fp16 A tiles
__device__ __align__(1024) __half g_bs0[(size_t)NCH0 * 32768];         // 3MB  split-fp16 W_ih0
__device__ __align__(1024) __half g_bs1[(size_t)NCH1 * 32768];         // 384KB split-fp16 W_ih1
__device__ float g_xg[(size_t)MTOT * GATES];   // 128MB gate pre-activations
__device__ float g_h1[(size_t)MTOT * HID];     // 32MB layer-0 hidden states
__device__ float g_hlast[BATCH * HID];

// ---------------- PTX helpers (all sm_103 baseline; NO tcgen05) ----------------
__device__ __forceinline__ uint32_t smem_u32(const void* p) {
    uint32_t a;
    asm("{ .reg .u64 t; cvta.to.shared.u64 t, %1; cvt.u32.u64 %0, t; }" : "=r"(a) : "l"(p));
    return a;
}
__device__ __forceinline__ void mbar_init(uint32_t m, uint32_t cnt) {
    asm volatile("mbarrier.init.shared.b64 [%0], %1;" :: "r"(m), "r"(cnt) : "memory");
}
__device__ __forceinline__ void mbar_expect_tx(uint32_t m, uint32_t b) {
    asm volatile("mbarrier.arrive.expect_tx.shared.b64 _, [%0], %1;" :: "r"(m), "r"(b) : "memory");
}
__device__ __forceinline__ void mbar_wait(uint32_t m, uint32_t ph) {
    asm volatile(
        "{\n\t.reg .pred P;\n\t"
        "WL_%=:\n\t"
        "mbarrier.try_wait.parity.shared.b64 P, [%0], %1;\n\t"
        "@P bra WD_%=;\n\t"
        "bra WL_%=;\n\t"
        "WD_%=:\n\t}"
        :: "r"(m), "r"(ph) : "memory");
}
__device__ __forceinline__ void bulk_g2s(uint32_t dst, const void* src, uint32_t bytes, uint32_t mbar) {
    asm volatile(
        "cp.async.bulk.shared::cluster.global.mbarrier::complete_tx::bytes [%0], [%1], %2, [%3];"
        :: "r"(dst), "l"(src), "r"(bytes), "r"(mbar) : "memory");
}
__device__ __forceinline__ void ldsm_x4(uint32_t& r0, uint32_t& r1, uint32_t& r2, uint32_t& r3,
                                        uint32_t a) {
    asm volatile("ldmatrix.sync.aligned.m8n8.x4.shared.b16 {%0,%1,%2,%3}, [%4];"
        : "=r"(r0), "=r"(r1), "=r"(r2), "=r"(r3) : "r"(a));
}
__device__ __forceinline__ void mma16816(float& d0, float& d1, float& d2, float& d3,
                                         uint32_t a0, uint32_t a1, uint32_t a2, uint32_t a3,
                                         uint32_t b0, uint32_t b1) {
    asm volatile("mma.sync.aligned.m16n8k16.row.col.f32.f16.f16.f32 "
        "{%0,%1,%2,%3},{%4,%5,%6,%7},{%8,%9},{%0,%1,%2,%3};"
        : "+f"(d0), "+f"(d1), "+f"(d2), "+f"(d3)
        : "r"(a0), "r"(a1), "r"(a2), "r"(a3), "r"(b0), "r"(b1));
}

// ---- packed f32x2 FMA (Blackwell FFMA2) ----
typedef unsigned long long u64b;
__device__ __forceinline__ void ffma2(u64b& d, u64b a, u64b b) {
    asm("fma.rn.f32x2 %0, %1, %2, %0;" : "+l"(d) : "l"(a), "l"(b));
}
__device__ __forceinline__ u64b pk64(float x, float y) {
    u64b r; asm("mov.b64 %0, {%1, %2};" : "=l"(r) : "f"(x), "f"(y)); return r;
}
__device__ __forceinline__ float2 upk64(u64b v) {
    float2 r; asm("mov.b64 {%0, %1}, %2;" : "=f"(r.x), "=f"(r.y) : "l"(v)); return r;
}

// ---------------- split-fp16 packing ----------------
__device__ __forceinline__ uint32_t pk2(float f0, float f1, bool lo) {
    __half h0 = __float2half_rn(f0);
    __half h1 = __float2half_rn(f1);
    if (lo) {
        h0 = __float2half_rn(f0 - __half2float(h0));
        h1 = __float2half_rn(f1 - __half2float(h1));
    }
    __half2 p = __halves2half2(h0, h1);
    return *reinterpret_cast<uint32_t*>(&p);
}

// ---------------- conversion: activations -> tiled+swizzled split-fp16 ----------------
__global__ void conv_a_kernel(const float* __restrict__ src, __half* __restrict__ dst,
                              int nchunk, int kshift)
{
    int idx = blockIdx.x * 256 + threadIdx.x;
    int u  = idx & 1023;
    int t2 = idx >> 10;
    int c  = t2 % nchunk;
    int mt = t2 / nchunk;
    int r = u >> 3, g = u & 7;
    int kk = c * 64 + g * 8;
    int slab = kk >> kshift;
    int k = kk - (slab << kshift);
    const float* xr = src + (((size_t)(mt * 128 + r)) << kshift) + k;
    float4 v0 = *(const float4*)xr;
    float4 v1 = *(const float4*)(xr + 4);
    bool lo = (slab == 2);
    uint4 o;
    o.x = pk2(v0.x, v0.y, lo);
    o.y = pk2(v0.z, v0.w, lo);
    o.z = pk2(v1.x, v1.y, lo);
    o.w = pk2(v1.z, v1.w, lo);
    uint32_t ob = (uint32_t)((r << 7) | (g << 4));
    uint32_t so = ob ^ ((ob >> 3) & 0x70);
    char* tile = (char*)(dst + (((size_t)(mt * nchunk + c)) << 13));
    *(uint4*)(tile + so) = o;
}

__global__ void conv_b_kernel(const float* __restrict__ w, __half* __restrict__ dst,
                              int kshift)
{
    int idx = blockIdx.x * 256 + threadIdx.x;
    int g = idx & 7;
    int n = (idx >> 3) & 511;
    int c = idx >> 12;
    int kk = c * 64 + g * 8;
    int slab = kk >> kshift;
    int k = kk - (slab << kshift);
    const float* wr = w + (((size_t)n) << kshift) + k;
    float4 v0 = *(const float4*)wr;
    float4 v1 = *(const float4*)(wr + 4);
    bool lo = (slab == 1);
    uint4 o;
    o.x = pk2(v0.x, v0.y, lo);
    o.y = pk2(v0.z, v0.w, lo);
    o.z = pk2(v1.x, v1.y, lo);
    o.w = pk2(v1.z, v1.w, lo);
    uint32_t ob = (uint32_t)((n << 7) | (g << 4));
    uint32_t so = ob ^ ((ob >> 3) & 0x70);
    char* chunk = (char*)(dst + (((size_t)c) << 15));
    *(uint4*)(chunk + so) = o;
}

// ---------------- HMMA GEMM: C[128 rows x 256 gates] per CTA (proven 428us, untouched) ----------------
#define GEMM_SMEM 152576
__global__ __launch_bounds__(512, 1) void gemm_hmma_kernel(
    const __half* __restrict__ Ap, const __half* __restrict__ Bp,
    const float* __restrict__ b1, const float* __restrict__ b2,
    float* __restrict__ C, int nchunk)
{
    extern __shared__ char smem_raw[];
    uint32_t sb0 = smem_u32(smem_raw);
    uint32_t ab = (sb0 + 1023) & ~1023u;                 // 1024-aligned base
    float* smbias = (float*)(smem_raw + (ab - sb0));     // 512 floats at offset 0

    const int tid = threadIdx.x;
    const int lane = tid & 31, wid = tid >> 5;
    const int wm = wid >> 2, wn = wid & 3;
    const int sub = lane >> 3, l7 = lane & 7;

    if (tid < 512) smbias[tid] = b1[tid] + b2[tid];
    if (tid == 0) {
        mbar_init(ab + 2048, 1); mbar_init(ab + 2056, 1); mbar_init(ab + 2064, 1);
    }
    __syncthreads();

    const int mt = blockIdx.x >> 1, j = blockIdx.x & 1;
    const char* Asrc = (const char*)Ap + ((size_t)mt * nchunk) * 16384;
    const char* Bsrc = (const char*)Bp + (size_t)j * 32768;

    if (tid == 0) {
        int npre = nchunk < 3 ? nchunk : 3;
        for (int c = 0; c < npre; c++) {
            uint32_t st = ab + 4096 + c * 49152;
            uint32_t mb = ab + 2048 + c * 8;
            mbar_expect_tx(mb, 49152);
            bulk_g2s(st,         Asrc + (size_t)c * 16384, 16384, mb);
            bulk_g2s(st + 16384, Bsrc + (size_t)c * 65536, 32768, mb);
        }
    }

    float acc[2][8][4];
#pragma unroll
    for (int a = 0; a < 2; a++)
#pragma unroll
        for (int b = 0; b < 8; b++)
#pragma unroll
            for (int d = 0; d < 4; d++) acc[a][b][d] = 0.0f;

    const uint32_t xorv = (uint32_t)(l7 << 4);
    const uint32_t arow = (uint32_t)((wm * 32 + (sub & 1) * 8 + l7) * 128);
    const uint32_t akh  = (uint32_t)((sub >> 1) * 16);
    const uint32_t brow = (uint32_t)((wn * 64 + (sub >> 1) * 8 + l7) * 128);
    const uint32_t bkh  = (uint32_t)((sub & 1) * 16);

    for (int c = 0; c < nchunk; c++) {
        int s = c % 3;
        uint32_t ph = (uint32_t)((c / 3) & 1);
        uint32_t mb_full = ab + 2048 + s * 8;
        mbar_wait(mb_full, ph);
        uint32_t Abase = ab + 4096 + s * 49152;
        uint32_t Bbase = Abase + 16384;

#pragma unroll
        for (int ks = 0; ks < 4; ks++) {
            uint32_t ak = ((uint32_t)(ks * 32) + akh) ^ xorv;
            uint32_t bk = ((uint32_t)(ks * 32) + bkh) ^ xorv;
            uint32_t a0[4], a1[4], bf[4][4];
            ldsm_x4(a0[0], a0[1], a0[2], a0[3], Abase + arow + ak);
            ldsm_x4(a1[0], a1[1], a1[2], a1[3], Abase + arow + 2048 + ak);
#pragma unroll
            for (int nb2 = 0; nb2 < 4; nb2++)
                ldsm_x4(bf[nb2][0], bf[nb2][1], bf[nb2][2], bf[nb2][3],
                        Bbase + brow + nb2 * 2048 + bk);
#pragma unroll
            for (int nb = 0; nb < 8; nb++) {
                uint32_t bb0 = bf[nb >> 1][(nb & 1) * 2];
                uint32_t bb1 = bf[nb >> 1][(nb & 1) * 2 + 1];
                mma16816(acc[0][nb][0], acc[0][nb][1], acc[0][nb][2], acc[0][nb][3],
                         a0[0], a0[1], a0[2], a0[3], bb0, bb1);
                mma16816(acc[1][nb][0], acc[1][nb][1], acc[1][nb][2], acc[1][nb][3],
                         a1[0], a1[1], a1[2], a1[3], bb0, bb1);
            }
        }
        __syncthreads();
        if (tid == 0 && c + 3 < nchunk) {
            uint32_t st = ab + 4096 + s * 49152;
            mbar_expect_tx(mb_full, 49152);
            bulk_g2s(st,         Asrc + (size_t)(c + 3) * 16384, 16384, mb_full);
            bulk_g2s(st + 16384, Bsrc + (size_t)(c + 3) * 65536, 32768, mb_full);
        }
    }

    const int mbase = mt * 128 + wm * 32 + (lane >> 2);
    const int colb  = j * 256 + wn * 64 + (lane & 3) * 2;
#pragma unroll
    for (int mb = 0; mb < 2; mb++)
#pragma unroll
        for (int nb = 0; nb < 8; nb++) {
            int cc = colb + nb * 8;
            float bx = smbias[cc], by = smbias[cc + 1];
            size_t r0 = (size_t)(mbase + mb * 16) * GATES + cc;
            float2 v0 = make_float2(acc[mb][nb][0] + bx, acc[mb][nb][1] + by);
            float2 v1 = make_float2(acc[mb][nb][2] + bx, acc[mb][nb][3] + by);
            *(float2*)(C + r0) = v0;
            *(float2*)(C + r0 + (size_t)8 * GATES) = v1;
        }
}

// ---------------- activations ----------------
__device__ __forceinline__ float sigmoidf_(float x) {
    return __fdividef(1.0f, 1.0f + __expf(-x));
}
__device__ __forceinline__ float tanhf_(float x) {
    float a = __expf(2.0f * fabsf(x));
    float r = 1.0f - __fdividef(2.0f, 1.0f + a);
    return copysignf(r, x);
}

// ---------------- LSTM recurrence: 256 thr, 96/32 reg split, shuffle gate exchange ----------------
// Thread tid = 2u+p owns gate rows u+128p (i/f) and u+128p+256 (g/o), so unit u's
// four activated gates live in adjacent lanes 2u,2u+1 -> exchanged via shfl_xor(1)
// (no gates smem round-trip). h double-buffered -> ONE __syncthreads per step.
// Per gate: k 0..95 in regs (48 u64b; 192 weight regs total, R10-proven budget),
// k 96..127 from smem indexed by thread slot (conflict-free float4).
#define REC_SMEM (8 * 512 * 16 + 2 * 128 * 4)
__global__ __launch_bounds__(256, 1) void lstm_rec_kernel(
    const float* __restrict__ xg, const float* __restrict__ w_hh,
    float* __restrict__ hout, float* __restrict__ hlast, int T)
{
    extern __shared__ float smem[];
    float4* sw = (float4*)smem;                 // [kc 0..7][slot 0..511] (k=96..127)
    float* hb0 = smem + 8 * 512 * 4;            // h buffer A (128)
    float* hb1 = hb0 + 128;                     // h buffer B (128)

    const int tid = threadIdx.x;
    const int b = blockIdx.x;
    const int u = tid >> 1;                      // hidden unit 0..127
    const int p = tid & 1;                       // 0: i/g  1: f/o
    const int rowA = u + (p << 7);               // i (p=0) or f (p=1): sigmoid
    const int rowB = rowA + 256;                 // g (p=0, tanh) or o (p=1, sigmoid)

    const float4* wrowA = (const float4*)(w_hh + (size_t)rowA * HID);
    const float4* wrowB = (const float4*)(w_hh + (size_t)rowB * HID);
    u64b wrA[48], wrB[48];
#pragma unroll
    for (int i = 0; i < 24; i++) {
        float4 va = wrowA[i];
        wrA[2 * i]     = pk64(va.x, va.y);
        wrA[2 * i + 1] = pk64(va.z, va.w);
        float4 vb = wrowB[i];
        wrB[2 * i]     = pk64(vb.x, vb.y);
        wrB[2 * i + 1] = pk64(vb.z, vb.w);
    }
#pragma unroll
    for (int kc = 0; kc < 8; kc++) {
        sw[kc * 512 + tid]       = wrowA[24 + kc];   // k = 96..127, slot-indexed
        sw[kc * 512 + 256 + tid] = wrowB[24 + kc];
    }

    if (tid < HID) hb0[tid] = 0.0f;
    float c = 0.0f, hval = 0.0f;
    __syncthreads();

    const float* xg_bA = xg + ((size_t)b * T) * GATES + rowA;
    const float* xg_bB = xg + ((size_t)b * T) * GATES + rowB;
    float xgA = xg_bA[0];
    float xgB = xg_bB[0];

    float* hcur = hb0;
    float* hnxt = hb1;

    for (int t = 0; t < T; t++) {
        float xgA_n = (t + 1 < T) ? xg_bA[(size_t)(t + 1) * GATES] : 0.0f;
        float xgB_n = (t + 1 < T) ? xg_bB[(size_t)(t + 1) * GATES] : 0.0f;

        u64b a0 = pk64(xgA, 0.0f), a1 = pk64(0.0f, 0.0f);
        u64b b0 = pk64(xgB, 0.0f), b1 = pk64(0.0f, 0.0f);
        const ulonglong2* h2 = (const ulonglong2*)hcur;
        // k = 0..95: h broadcast + register weights (4 independent FFMA2 chains)
#pragma unroll
        for (int i = 0; i < 24; i++) {
            ulonglong2 hv = h2[i];
            ffma2(a0, hv.x, wrA[2 * i]);
            ffma2(a1, hv.y, wrA[2 * i + 1]);
            ffma2(b0, hv.x, wrB[2 * i]);
            ffma2(b1, hv.y, wrB[2 * i + 1]);
        }
        // k = 96..127: weights from smem (slot-indexed, conflict-free)
#pragma unroll
        for (int kc = 0; kc < 8; kc++) {
            ulonglong2 hv = h2[24 + kc];
            float4 wa = sw[kc * 512 + tid];
            ulonglong2 wau = *reinterpret_cast<ulonglong2*>(&wa);
            ffma2(a0, hv.x, wau.x);
            ffma2(a1, hv.y, wau.y);
            float4 wb = sw[kc * 512 + 256 + tid];
            ulonglong2 wbu = *reinterpret_cast<ulonglong2*>(&wb);
            ffma2(b0, hv.x, wbu.x);
            ffma2(b1, hv.y, wbu.y);
        }
        float2 fa0 = upk64(a0), fa1 = upk64(a1);
        float2 fb0 = upk64(b0), fb1 = upk64(b1);
        float preA = (fa0.x + fa0.y) + (fa1.x + fa1.y);
        float preB = (fb0.x + fb0.y) + (fb1.x + fb1.y);

        float actA = sigmoidf_(preA);                           // i or f
        float actB = p ? sigmoidf_(preB) : tanhf_(preB);        // o or g
        float pa = __shfl_xor_sync(0xffffffffu, actA, 1);
        float pb = __shfl_xor_sync(0xffffffffu, actB, 1);
        float ig = p ? pa : actA;
        float fg = p ? actA : pa;
        float gg = p ? pb : actB;
        float og = p ? actB : pb;
        c = fg * c + ig * gg;                                   // redundant in both lanes
        hval = og * tanhf_(c);
        if (p == 0) {
            hnxt[u] = hval;
            if (hout) hout[((size_t)b * T + t) * HID + u] = hval;
        }
        __syncthreads();                                        // ONE barrier per step
        float* tmp = hcur; hcur = hnxt; hnxt = tmp;
        xgA = xgA_n;
        xgB = xgB_n;
    }
    if (hlast && p == 0) hlast[b * HID + u] = hval;
}

// ---------------- final FC ----------------
__global__ void fc_kernel(const float* __restrict__ hlast, const float* __restrict__ fc_w,
                          const float* __restrict__ fc_b, float* __restrict__ out)
{
    int tid = threadIdx.x;
    int b = tid >> 3;
    int cls = tid & 7;
    const float* hv = hlast + b * HID;
    const float* wv = fc_w + cls * HID;
    float s = fc_b[cls];
#pragma unroll 8
    for (int j = 0; j < HID; j++) s += hv[j] * wv[j];
    out[b * NCLS + cls] = s;
}

// ---------------- launch ----------------
extern "C" void kernel_launch(void* const* d_in, const int* in_sizes, int n_in,
                              void* d_out, int out_size)
{
    const float* x     = (const float*)d_in[0];
    const float* w_ih0 = (const float*)d_in[1];
    const float* w_hh0 = (const float*)d_in[2];
    const float* b_ih0 = (const float*)d_in[3];
    const float* b_hh0 = (const float*)d_in[4];
    const float* w_ih1 = (const float*)d_in[5];
    const float* w_hh1 = (const float*)d_in[6];
    const float* b_ih1 = (const float*)d_in[7];
    const float* b_hh1 = (const float*)d_in[8];
    const float* fc_w  = (const float*)d_in[9];
    const float* fc_b  = (const float*)d_in[10];
    float* out = (float*)d_out;

    float *xg_p = nullptr, *h1_p = nullptr, *hl_p = nullptr;
    __half *as_p = nullptr, *bs0_p = nullptr, *bs1_p = nullptr;
    cudaGetSymbolAddress((void**)&xg_p, g_xg);
    cudaGetSymbolAddress((void**)&h1_p, g_h1);
    cudaGetSymbolAddress((void**)&hl_p, g_hlast);
    cudaGetSymbolAddress((void**)&as_p, g_as);
    cudaGetSymbolAddress((void**)&bs0_p, g_bs0);
    cudaGetSymbolAddress((void**)&bs1_p, g_bs1);

    cudaFuncSetAttribute(lstm_rec_kernel,
                         cudaFuncAttributeMaxDynamicSharedMemorySize, REC_SMEM);
    cudaFuncSetAttribute(gemm_hmma_kernel,
                         cudaFuncAttributeMaxDynamicSharedMemorySize, GEMM_SMEM);

    // weight conversions (tiny)
    conv_b_kernel<<<NCH0 * 512 * 8 / 256, 256>>>(w_ih0, bs0_p, 10);
    conv_b_kernel<<<NCH1 * 512 * 8 / 256, 256>>>(w_ih1, bs1_p, 7);

    // layer 0: x -> split-fp16 tiles -> HMMA GEMM -> recurrence
    conv_a_kernel<<<MTILES * NCH0 * 1024 / 256, 256>>>(x, as_p, NCH0, 10);
    gemm_hmma_kernel<<<MTILES * 2, 512, GEMM_SMEM>>>(as_p, bs0_p, b_ih0, b_hh0, xg_p, NCH0);
    lstm_rec_kernel<<<BATCH, 256, REC_SMEM>>>(xg_p, w_hh0, h1_p, nullptr, SEQT);

    // layer 1: h1 -> split-fp16 tiles -> HMMA GEMM -> recurrence
    conv_a_kernel<<<MTILES * NCH1 * 1024 / 256, 256>>>(h1_p, as_p, NCH1, 7);
    gemm_hmma_kernel<<<MTILES * 2, 512, GEMM_SMEM>>>(as_p, bs1_p, b_ih1, b_hh1, xg_p, NCH1);
    lstm_rec_kernel<<<BATCH, 256, REC_SMEM>>>(xg_p, w_hh1, nullptr, hl_p, SEQT);

    // FC head
    fc_kernel<<<1, BATCH * NCLS>>>(hl_p, fc_w, fc_b, out);
}

// round 13
// speedup vs baseline: 1.0560x; 1.0286x over previous
#include <cuda_runtime.h>
#include <cuda_fp16.h>
#include <cstdint>

// Problem constants
#define BATCH 128
#define SEQT  512
#define DIN   1024
#define HID   128
#define GATES 512
#define NCLS  8
#define MTOT  (BATCH * SEQT)      // 65536
#define MTILES (MTOT / 128)       // 512
#define NCH0  48                  // 3*1024/64 k-chunks, layer 0
#define NCH1  6                   // 3*128/64  k-chunks, layer 1

// ---------------- scratch (device globals; no allocation) ----------------
__device__ __align__(1024) __half g_as[(size_t)MTILES * NCH0 * 8192];  // 384MB split-fp16 A tiles
__device__ __align__(1024) __half g_bs0[(size_t)NCH0 * 32768];         // 3MB  split-fp16 W_ih0
__device__ __align__(1024) __half g_bs1[(size_t)NCH1 * 32768];         // 384KB split-fp16 W_ih1
__device__ float g_xg[(size_t)MTOT * GATES];   // 128MB gate pre-activations
__device__ float g_hlast[BATCH * HID];

// ---------------- PTX helpers (all sm_103 baseline; NO tcgen05) ----------------
__device__ __forceinline__ uint32_t smem_u32(const void* p) {
    uint32_t a;
    asm("{ .reg .u64 t; cvta.to.shared.u64 t, %1; cvt.u32.u64 %0, t; }" : "=r"(a) : "l"(p));
    return a;
}
__device__ __forceinline__ void mbar_init(uint32_t m, uint32_t cnt) {
    asm volatile("mbarrier.init.shared.b64 [%0], %1;" :: "r"(m), "r"(cnt) : "memory");
}
__device__ __forceinline__ void mbar_expect_tx(uint32_t m, uint32_t b) {
    asm volatile("mbarrier.arrive.expect_tx.shared.b64 _, [%0], %1;" :: "r"(m), "r"(b) : "memory");
}
__device__ __forceinline__ void mbar_wait(uint32_t m, uint32_t ph) {
    asm volatile(
        "{\n\t.reg .pred P;\n\t"
        "WL_%=:\n\t"
        "mbarrier.try_wait.parity.shared.b64 P, [%0], %1;\n\t"
        "@P bra WD_%=;\n\t"
        "bra WL_%=;\n\t"
        "WD_%=:\n\t}"
        :: "r"(m), "r"(ph) : "memory");
}
__device__ __forceinline__ void bulk_g2s(uint32_t dst, const void* src, uint32_t bytes, uint32_t mbar) {
    asm volatile(
        "cp.async.bulk.shared::cluster.global.mbarrier::complete_tx::bytes [%0], [%1], %2, [%3];"
        :: "r"(dst), "l"(src), "r"(bytes), "r"(mbar) : "memory");
}
__device__ __forceinline__ void ldsm_x4(uint32_t& r0, uint32_t& r1, uint32_t& r2, uint32_t& r3,
                                        uint32_t a) {
    asm volatile("ldmatrix.sync.aligned.m8n8.x4.shared.b16 {%0,%1,%2,%3}, [%4];"
        : "=r"(r0), "=r"(r1), "=r"(r2), "=r"(r3) : "r"(a));
}
__device__ __forceinline__ void mma16816(float& d0, float& d1, float& d2, float& d3,
                                         uint32_t a0, uint32_t a1, uint32_t a2, uint32_t a3,
                                         uint32_t b0, uint32_t b1) {
    asm volatile("mma.sync.aligned.m16n8k16.row.col.f32.f16.f16.f32 "
        "{%0,%1,%2,%3},{%4,%5,%6,%7},{%8,%9},{%0,%1,%2,%3};"
        : "+f"(d0), "+f"(d1), "+f"(d2), "+f"(d3)
        : "r"(a0), "r"(a1), "r"(a2), "r"(a3), "r"(b0), "r"(b1));
}

// ---- packed f32x2 FMA (Blackwell FFMA2) ----
typedef unsigned long long u64b;
__device__ __forceinline__ void ffma2(u64b& d, u64b a, u64b b) {
    asm("fma.rn.f32x2 %0, %1, %2, %0;" : "+l"(d) : "l"(a), "l"(b));
}
__device__ __forceinline__ u64b pk64(float x, float y) {
    u64b r; asm("mov.b64 %0, {%1, %2};" : "=l"(r) : "f"(x), "f"(y)); return r;
}
__device__ __forceinline__ float2 upk64(u64b v) {
    float2 r; asm("mov.b64 {%0, %1}, %2;" : "=f"(r.x), "=f"(r.y) : "l"(v)); return r;
}

// ---------------- split-fp16 packing ----------------
__device__ __forceinline__ uint32_t pk2(float f0, float f1, bool lo) {
    __half h0 = __float2half_rn(f0);
    __half h1 = __float2half_rn(f1);
    if (lo) {
        h0 = __float2half_rn(f0 - __half2float(h0));
        h1 = __float2half_rn(f1 - __half2float(h1));
    }
    __half2 p = __halves2half2(h0, h1);
    return *reinterpret_cast<uint32_t*>(&p);
}

// ---------------- conversion: activations -> tiled+swizzled split-fp16 (layer 0 only) ----------------
// A' layout: [mt][chunk][128 rows x 64 fp16, SW128] (16KB tiles)
// slabs along logical K' = 3K: [hi | hi | lo]
__global__ void conv_a_kernel(const float* __restrict__ src, __half* __restrict__ dst,
                              int nchunk, int kshift)
{
    int idx = blockIdx.x * 256 + threadIdx.x;
    int u  = idx & 1023;
    int t2 = idx >> 10;
    int c  = t2 % nchunk;
    int mt = t2 / nchunk;
    int r = u >> 3, g = u & 7;
    int kk = c * 64 + g * 8;
    int slab = kk >> kshift;
    int k = kk - (slab << kshift);
    const float* xr = src + (((size_t)(mt * 128 + r)) << kshift) + k;
    float4 v0 = *(const float4*)xr;
    float4 v1 = *(const float4*)(xr + 4);
    bool lo = (slab == 2);
    uint4 o;
    o.x = pk2(v0.x, v0.y, lo);
    o.y = pk2(v0.z, v0.w, lo);
    o.z = pk2(v1.x, v1.y, lo);
    o.w = pk2(v1.z, v1.w, lo);
    uint32_t ob = (uint32_t)((r << 7) | (g << 4));
    uint32_t so = ob ^ ((ob >> 3) & 0x70);
    char* tile = (char*)(dst + (((size_t)(mt * nchunk + c)) << 13));
    *(uint4*)(tile + so) = o;
}

// weights -> [chunk][512 rows x 64 fp16, SW128-swizzled] (64KB chunks)
// slabs along K': [hi | lo | hi]  (pairs with A's [hi | hi | lo])
__global__ void conv_b_kernel(const float* __restrict__ w, __half* __restrict__ dst,
                              int kshift)
{
    int idx = blockIdx.x * 256 + threadIdx.x;
    int g = idx & 7;
    int n = (idx >> 3) & 511;
    int c = idx >> 12;
    int kk = c * 64 + g * 8;
    int slab = kk >> kshift;
    int k = kk - (slab << kshift);
    const float* wr = w + (((size_t)n) << kshift) + k;
    float4 v0 = *(const float4*)wr;
    float4 v1 = *(const float4*)(wr + 4);
    bool lo = (slab == 1);
    uint4 o;
    o.x = pk2(v0.x, v0.y, lo);
    o.y = pk2(v0.z, v0.w, lo);
    o.z = pk2(v1.x, v1.y, lo);
    o.w = pk2(v1.z, v1.w, lo);
    uint32_t ob = (uint32_t)((n << 7) | (g << 4));
    uint32_t so = ob ^ ((ob >> 3) & 0x70);
    char* chunk = (char*)(dst + (((size_t)c) << 15));
    *(uint4*)(chunk + so) = o;
}

// ---------------- HMMA GEMM: C[128 rows x 256 gates] per CTA (proven 428us, untouched) ----------------
#define GEMM_SMEM 152576
__global__ __launch_bounds__(512, 1) void gemm_hmma_kernel(
    const __half* __restrict__ Ap, const __half* __restrict__ Bp,
    const float* __restrict__ b1, const float* __restrict__ b2,
    float* __restrict__ C, int nchunk)
{
    extern __shared__ char smem_raw[];
    uint32_t sb0 = smem_u32(smem_raw);
    uint32_t ab = (sb0 + 1023) & ~1023u;                 // 1024-aligned base
    float* smbias = (float*)(smem_raw + (ab - sb0));     // 512 floats at offset 0

    const int tid = threadIdx.x;
    const int lane = tid & 31, wid = tid >> 5;
    const int wm = wid >> 2, wn = wid & 3;
    const int sub = lane >> 3, l7 = lane & 7;

    if (tid < 512) smbias[tid] = b1[tid] + b2[tid];
    if (tid == 0) {
        mbar_init(ab + 2048, 1); mbar_init(ab + 2056, 1); mbar_init(ab + 2064, 1);
    }
    __syncthreads();

    const int mt = blockIdx.x >> 1, j = blockIdx.x & 1;
    const char* Asrc = (const char*)Ap + ((size_t)mt * nchunk) * 16384;
    const char* Bsrc = (const char*)Bp + (size_t)j * 32768;

    if (tid == 0) {
        int npre = nchunk < 3 ? nchunk : 3;
        for (int c = 0; c < npre; c++) {
            uint32_t st = ab + 4096 + c * 49152;
            uint32_t mb = ab + 2048 + c * 8;
            mbar_expect_tx(mb, 49152);
            bulk_g2s(st,         Asrc + (size_t)c * 16384, 16384, mb);
            bulk_g2s(st + 16384, Bsrc + (size_t)c * 65536, 32768, mb);
        }
    }

    float acc[2][8][4];
#pragma unroll
    for (int a = 0; a < 2; a++)
#pragma unroll
        for (int b = 0; b < 8; b++)
#pragma unroll
            for (int d = 0; d < 4; d++) acc[a][b][d] = 0.0f;

    const uint32_t xorv = (uint32_t)(l7 << 4);
    const uint32_t arow = (uint32_t)((wm * 32 + (sub & 1) * 8 + l7) * 128);
    const uint32_t akh  = (uint32_t)((sub >> 1) * 16);
    const uint32_t brow = (uint32_t)((wn * 64 + (sub >> 1) * 8 + l7) * 128);
    const uint32_t bkh  = (uint32_t)((sub & 1) * 16);

    for (int c = 0; c < nchunk; c++) {
        int s = c % 3;
        uint32_t ph = (uint32_t)((c / 3) & 1);
        uint32_t mb_full = ab + 2048 + s * 8;
        mbar_wait(mb_full, ph);
        uint32_t Abase = ab + 4096 + s * 49152;
        uint32_t Bbase = Abase + 16384;

#pragma unroll
        for (int ks = 0; ks < 4; ks++) {
            uint32_t ak = ((uint32_t)(ks * 32) + akh) ^ xorv;
            uint32_t bk = ((uint32_t)(ks * 32) + bkh) ^ xorv;
            uint32_t a0[4], a1[4], bf[4][4];
            ldsm_x4(a0[0], a0[1], a0[2], a0[3], Abase + arow + ak);
            ldsm_x4(a1[0], a1[1], a1[2], a1[3], Abase + arow + 2048 + ak);
#pragma unroll
            for (int nb2 = 0; nb2 < 4; nb2++)
                ldsm_x4(bf[nb2][0], bf[nb2][1], bf[nb2][2], bf[nb2][3],
                        Bbase + brow + nb2 * 2048 + bk);
#pragma unroll
            for (int nb = 0; nb < 8; nb++) {
                uint32_t bb0 = bf[nb >> 1][(nb & 1) * 2];
                uint32_t bb1 = bf[nb >> 1][(nb & 1) * 2 + 1];
                mma16816(acc[0][nb][0], acc[0][nb][1], acc[0][nb][2], acc[0][nb][3],
                         a0[0], a0[1], a0[2], a0[3], bb0, bb1);
                mma16816(acc[1][nb][0], acc[1][nb][1], acc[1][nb][2], acc[1][nb][3],
                         a1[0], a1[1], a1[2], a1[3], bb0, bb1);
            }
        }
        __syncthreads();
        if (tid == 0 && c + 3 < nchunk) {
            uint32_t st = ab + 4096 + s * 49152;
            mbar_expect_tx(mb_full, 49152);
            bulk_g2s(st,         Asrc + (size_t)(c + 3) * 16384, 16384, mb_full);
            bulk_g2s(st + 16384, Bsrc + (size_t)(c + 3) * 65536, 32768, mb_full);
        }
    }

    const int mbase = mt * 128 + wm * 32 + (lane >> 2);
    const int colb  = j * 256 + wn * 64 + (lane & 3) * 2;
#pragma unroll
    for (int mb = 0; mb < 2; mb++)
#pragma unroll
        for (int nb = 0; nb < 8; nb++) {
            int cc = colb + nb * 8;
            float bx = smbias[cc], by = smbias[cc + 1];
            size_t r0 = (size_t)(mbase + mb * 16) * GATES + cc;
            float2 v0 = make_float2(acc[mb][nb][0] + bx, acc[mb][nb][1] + by);
            float2 v1 = make_float2(acc[mb][nb][2] + bx, acc[mb][nb][3] + by);
            *(float2*)(C + r0) = v0;
            *(float2*)(C + r0 + (size_t)8 * GATES) = v1;
        }
}

// ---------------- activations ----------------
__device__ __forceinline__ float sigmoidf_(float x) {
    return __fdividef(1.0f, 1.0f + __expf(-x));
}
__device__ __forceinline__ float tanhf_(float x) {
    float a = __expf(2.0f * fabsf(x));
    float r = 1.0f - __fdividef(2.0f, 1.0f + a);
    return copysignf(r, x);
}

// ---------------- LSTM recurrence: R10-exact structure (256 thr, 2 gates/thr, 96/32) ----------------
// NEW: when aout != nullptr, writer threads emit h directly as split-fp16 into the
// layer-1 A-tile layout (hi -> chunks u>>6 and u>>6+2, lo -> u>>6+4), replacing the
// separate h1 buffer + conv_a1 kernel. Bit-identical bytes to conv_a_kernel's output.
#define REC_SMEM (8 * 512 * 16 + 128 * 4 + 512 * 4)
__global__ __launch_bounds__(256, 1) void lstm_rec_kernel(
    const float* __restrict__ xg, const float* __restrict__ w_hh,
    __half* __restrict__ aout, float* __restrict__ hlast, int T)
{
    extern __shared__ float smem[];
    float4* sw = (float4*)smem;                 // [kc 0..7][row 0..511] float4 (k=96..127)
    float* h_s = smem + 8 * 512 * 4;            // 128 floats
    float* gates = h_s + 128;                   // 512 floats (activated)

    const int tid = threadIdx.x;
    const int b = blockIdx.x;
    const int rowA = tid;                        // i (0..127) / f (128..255): sigmoid
    const int rowB = tid + 256;                  // g (256..383): tanh / o (384..511): sigmoid
    const bool b_is_tanh = (tid < 128);

    const float4* wrowA = (const float4*)(w_hh + (size_t)rowA * HID);
    const float4* wrowB = (const float4*)(w_hh + (size_t)rowB * HID);
    u64b wrA[48], wrB[48];
#pragma unroll
    for (int i = 0; i < 24; i++) {
        float4 va = wrowA[i];
        wrA[2 * i]     = pk64(va.x, va.y);
        wrA[2 * i + 1] = pk64(va.z, va.w);
        float4 vb = wrowB[i];
        wrB[2 * i]     = pk64(vb.x, vb.y);
        wrB[2 * i + 1] = pk64(vb.z, vb.w);
    }
#pragma unroll
    for (int kc = 0; kc < 8; kc++) {
        sw[kc * 512 + rowA] = wrowA[24 + kc];   // k = 96..127
        sw[kc * 512 + rowB] = wrowB[24 + kc];
    }

    if (tid < HID) h_s[tid] = 0.0f;
    float c = 0.0f;
    __syncthreads();

    const float* xg_bA = xg + ((size_t)b * T) * GATES + rowA;
    const float* xg_bB = xg + ((size_t)b * T) * GATES + rowB;
    float xgA = xg_bA[0];
    float xgB = xg_bB[0];

    // constants for fused A-tile write (writer threads tid < 128 only)
    const uint32_t cb = (uint32_t)((tid & 63) * 2);   // byte column within tile row
    char* abase_u = aout ? ((char*)aout + (((size_t)(tid >> 6)) << 14)) : nullptr;

    for (int t = 0; t < T; t++) {
        float xgA_n = (t + 1 < T) ? xg_bA[(size_t)(t + 1) * GATES] : 0.0f;
        float xgB_n = (t + 1 < T) ? xg_bB[(size_t)(t + 1) * GATES] : 0.0f;

        u64b a0 = pk64(xgA, 0.0f), a1 = pk64(0.0f, 0.0f);
        u64b b0 = pk64(xgB, 0.0f), b1 = pk64(0.0f, 0.0f);
        const ulonglong2* h2 = (const ulonglong2*)h_s;
        // k = 0..95: h broadcast + register weights, 4 independent chains
#pragma unroll
        for (int i = 0; i < 24; i++) {
            ulonglong2 hv = h2[i];
            ffma2(a0, hv.x, wrA[2 * i]);
            ffma2(a1, hv.y, wrA[2 * i + 1]);
            ffma2(b0, hv.x, wrB[2 * i]);
            ffma2(b1, hv.y, wrB[2 * i + 1]);
        }
        // k = 96..127: weights from smem
#pragma unroll
        for (int kc = 0; kc < 8; kc++) {
            ulonglong2 hv = h2[24 + kc];
            float4 wa = sw[kc * 512 + rowA];
            ulonglong2 wau = *reinterpret_cast<ulonglong2*>(&wa);
            ffma2(a0, hv.x, wau.x);
            ffma2(a1, hv.y, wau.y);
            float4 wb = sw[kc * 512 + rowB];
            ulonglong2 wbu = *reinterpret_cast<ulonglong2*>(&wb);
            ffma2(b0, hv.x, wbu.x);
            ffma2(b1, hv.y, wbu.y);
        }
        float2 fa0 = upk64(a0), fa1 = upk64(a1);
        float2 fb0 = upk64(b0), fb1 = upk64(b1);
        float preA = (fa0.x + fa0.y) + (fa1.x + fa1.y);
        float preB = (fb0.x + fb0.y) + (fb1.x + fb1.y);
        gates[rowA] = sigmoidf_(preA);                                // i or f
        gates[rowB] = b_is_tanh ? tanhf_(preB) : sigmoidf_(preB);     // g or o
        __syncthreads();

        if (tid < HID) {
            float ig = gates[tid];
            float fg = gates[HID + tid];
            float gg = gates[2 * HID + tid];
            float og = gates[3 * HID + tid];
            c = fg * c + ig * gg;
            float h = og * tanhf_(c);
            h_s[tid] = h;
            if (aout) {
                // fused layer-1 A-tile write: m = b*512 + t; r = t&127; mt = 4b + t>>7
                int r = t & 127;
                int mtl = (b << 2) | (t >> 7);
                uint32_t ob = (uint32_t)(r << 7) | cb;
                uint32_t so = ob ^ ((ob >> 3) & 0x70);
                char* dst = abase_u + (((size_t)mtl * 6) << 14) + so;
                __half hi = __float2half_rn(h);
                __half lo = __float2half_rn(h - __half2float(hi));
                *(__half*)(dst)         = hi;   // slab0 hi: chunk (tid>>6)
                *(__half*)(dst + 32768) = hi;   // slab1 hi: chunk (tid>>6)+2
                *(__half*)(dst + 65536) = lo;   // slab2 lo: chunk (tid>>6)+4
            }
        }
        __syncthreads();
        xgA = xgA_n;
        xgB = xgB_n;
    }
    if (hlast && tid < HID) hlast[b * HID + tid] = h_s[tid];
}

// ---------------- final FC ----------------
__global__ void fc_kernel(const float* __restrict__ hlast, const float* __restrict__ fc_w,
                          const float* __restrict__ fc_b, float* __restrict__ out)
{
    int tid = threadIdx.x;
    int b = tid >> 3;
    int cls = tid & 7;
    const float* hv = hlast + b * HID;
    const float* wv = fc_w + cls * HID;
    float s = fc_b[cls];
#pragma unroll 8
    for (int j = 0; j < HID; j++) s += hv[j] * wv[j];
    out[b * NCLS + cls] = s;
}

// ---------------- launch ----------------
extern "C" void kernel_launch(void* const* d_in, const int* in_sizes, int n_in,
                              void* d_out, int out_size)
{
    const float* x     = (const float*)d_in[0];
    const float* w_ih0 = (const float*)d_in[1];
    const float* w_hh0 = (const float*)d_in[2];
    const float* b_ih0 = (const float*)d_in[3];
    const float* b_hh0 = (const float*)d_in[4];
    const float* w_ih1 = (const float*)d_in[5];
    const float* w_hh1 = (const float*)d_in[6];
    const float* b_ih1 = (const float*)d_in[7];
    const float* b_hh1 = (const float*)d_in[8];
    const float* fc_w  = (const float*)d_in[9];
    const float* fc_b  = (const float*)d_in[10];
    float* out = (float*)d_out;

    float *xg_p = nullptr, *hl_p = nullptr;
    __half *as_p = nullptr, *bs0_p = nullptr, *bs1_p = nullptr;
    cudaGetSymbolAddress((void**)&xg_p, g_xg);
    cudaGetSymbolAddress((void**)&hl_p, g_hlast);
    cudaGetSymbolAddress((void**)&as_p, g_as);
    cudaGetSymbolAddress((void**)&bs0_p, g_bs0);
    cudaGetSymbolAddress((void**)&bs1_p, g_bs1);

    cudaFuncSetAttribute(lstm_rec_kernel,
                         cudaFuncAttributeMaxDynamicSharedMemorySize, REC_SMEM);
    cudaFuncSetAttribute(gemm_hmma_kernel,
                         cudaFuncAttributeMaxDynamicSharedMemorySize, GEMM_SMEM);

    // weight conversions (tiny)
    conv_b_kernel<<<NCH0 * 512 * 8 / 256, 256>>>(w_ih0, bs0_p, 10);
    conv_b_kernel<<<NCH1 * 512 * 8 / 256, 256>>>(w_ih1, bs1_p, 7);

    // layer 0: x -> split-fp16 tiles -> HMMA GEMM -> recurrence (writes layer-1 A tiles)
    conv_a_kernel<<<MTILES * NCH0 * 1024 / 256, 256>>>(x, as_p, NCH0, 10);
    gemm_hmma_kernel<<<MTILES * 2, 512, GEMM_SMEM>>>(as_p, bs0_p, b_ih0, b_hh0, xg_p, NCH0);
    lstm_rec_kernel<<<BATCH, 256, REC_SMEM>>>(xg_p, w_hh0, as_p, nullptr, SEQT);

    // layer 1: (A tiles already written by rec0) -> HMMA GEMM -> recurrence
    gemm_hmma_kernel<<<MTILES * 2, 512, GEMM_SMEM>>>(as_p, bs1_p, b_ih1, b_hh1, xg_p, NCH1);
    lstm_rec_kernel<<<BATCH, 256, REC_SMEM>>>(xg_p, w_hh1, nullptr, hl_p, SEQT);

    // FC head
    fc_kernel<<<1, BATCH * NCLS>>>(hl_p, fc_w, fc_b, out);
}

// round 14
// speedup vs baseline: 1.0621x; 1.0058x over previous
#include <cuda_runtime.h>
#include <cuda_fp16.h>
#include <cstdint>

// Problem constants
#define BATCH 128
#define SEQT  512
#define DIN   1024
#define HID   128
#define GATES 512
#define NCLS  8
#define MTOT  (BATCH * SEQT)      // 65536
#define MTILES (MTOT / 128)       // 512
#define NCH0  48                  // 3*1024/64 logical k-chunks, layer 0
#define NCH1  6                   // 3*128/64  logical k-chunks, layer 1
#define NSC0  (NCH0 / 2)          // 24 super-chunks (K=128 each)
#define NSC1  (NCH1 / 2)          // 3 super-chunks

// ---------------- scratch (device globals; no allocation) ----------------
__device__ __align__(1024) __half g_as[(size_t)MTILES * NCH0 * 8192];  // 384MB split-fp16 A tiles
__device__ __align__(1024) __half g_bs0[(size_t)NCH0 * 32768];         // 3MB  split-fp16 W_ih0
__device__ __align__(1024) __half g_bs1[(size_t)NCH1 * 32768];         // 384KB split-fp16 W_ih1
__device__ float g_xg[(size_t)MTOT * GATES];   // 128MB gate pre-activations
__device__ float g_h1[(size_t)MTOT * HID];     // 32MB layer-0 hidden states
__device__ float g_hlast[BATCH * HID];

// ---------------- PTX helpers (all sm_103 baseline; NO tcgen05) ----------------
__device__ __forceinline__ uint32_t smem_u32(const void* p) {
    uint32_t a;
    asm("{ .reg .u64 t; cvta.to.shared.u64 t, %1; cvt.u32.u64 %0, t; }" : "=r"(a) : "l"(p));
    return a;
}
__device__ __forceinline__ void mbar_init(uint32_t m, uint32_t cnt) {
    asm volatile("mbarrier.init.shared.b64 [%0], %1;" :: "r"(m), "r"(cnt) : "memory");
}
__device__ __forceinline__ void mbar_expect_tx(uint32_t m, uint32_t b) {
    asm volatile("mbarrier.arrive.expect_tx.shared.b64 _, [%0], %1;" :: "r"(m), "r"(b) : "memory");
}
__device__ __forceinline__ void mbar_wait(uint32_t m, uint32_t ph) {
    asm volatile(
        "{\n\t.reg .pred P;\n\t"
        "WL_%=:\n\t"
        "mbarrier.try_wait.parity.shared.b64 P, [%0], %1;\n\t"
        "@P bra WD_%=;\n\t"
        "bra WL_%=;\n\t"
        "WD_%=:\n\t}"
        :: "r"(m), "r"(ph) : "memory");
}
__device__ __forceinline__ void bulk_g2s(uint32_t dst, const void* src, uint32_t bytes, uint32_t mbar) {
    asm volatile(
        "cp.async.bulk.shared::cluster.global.mbarrier::complete_tx::bytes [%0], [%1], %2, [%3];"
        :: "r"(dst), "l"(src), "r"(bytes), "r"(mbar) : "memory");
}
__device__ __forceinline__ void ldsm_x4(uint32_t& r0, uint32_t& r1, uint32_t& r2, uint32_t& r3,
                                        uint32_t a) {
    asm volatile("ldmatrix.sync.aligned.m8n8.x4.shared.b16 {%0,%1,%2,%3}, [%4];"
        : "=r"(r0), "=r"(r1), "=r"(r2), "=r"(r3) : "r"(a));
}
__device__ __forceinline__ void mma16816(float& d0, float& d1, float& d2, float& d3,
                                         uint32_t a0, uint32_t a1, uint32_t a2, uint32_t a3,
                                         uint32_t b0, uint32_t b1) {
    asm volatile("mma.sync.aligned.m16n8k16.row.col.f32.f16.f16.f32 "
        "{%0,%1,%2,%3},{%4,%5,%6,%7},{%8,%9},{%0,%1,%2,%3};"
        : "+f"(d0), "+f"(d1), "+f"(d2), "+f"(d3)
        : "r"(a0), "r"(a1), "r"(a2), "r"(a3), "r"(b0), "r"(b1));
}

// ---- packed f32x2 FMA (Blackwell FFMA2) ----
typedef unsigned long long u64b;
__device__ __forceinline__ void ffma2(u64b& d, u64b a, u64b b) {
    asm("fma.rn.f32x2 %0, %1, %2, %0;" : "+l"(d) : "l"(a), "l"(b));
}
__device__ __forceinline__ u64b pk64(float x, float y) {
    u64b r; asm("mov.b64 %0, {%1, %2};" : "=l"(r) : "f"(x), "f"(y)); return r;
}
__device__ __forceinline__ float2 upk64(u64b v) {
    float2 r; asm("mov.b64 {%0, %1}, %2;" : "=f"(r.x), "=f"(r.y) : "l"(v)); return r;
}

// ---------------- split-fp16 packing ----------------
__device__ __forceinline__ uint32_t pk2(float f0, float f1, bool lo) {
    __half h0 = __float2half_rn(f0);
    __half h1 = __float2half_rn(f1);
    if (lo) {
        h0 = __float2half_rn(f0 - __half2float(h0));
        h1 = __float2half_rn(f1 - __half2float(h1));
    }
    __half2 p = __halves2half2(h0, h1);
    return *reinterpret_cast<uint32_t*>(&p);
}

// ---------------- conversion: activations -> tiled+swizzled split-fp16 ----------------
// A' layout: [mt][chunk][128 rows x 64 fp16, SW128] (16KB tiles)
// slabs along logical K' = 3K: [hi | hi | lo]
__global__ void conv_a_kernel(const float* __restrict__ src, __half* __restrict__ dst,
                              int nchunk, int kshift)
{
    int idx = blockIdx.x * 256 + threadIdx.x;
    int u  = idx & 1023;
    int t2 = idx >> 10;
    int c  = t2 % nchunk;
    int mt = t2 / nchunk;
    int r = u >> 3, g = u & 7;
    int kk = c * 64 + g * 8;
    int slab = kk >> kshift;
    int k = kk - (slab << kshift);
    const float* xr = src + (((size_t)(mt * 128 + r)) << kshift) + k;
    float4 v0 = *(const float4*)xr;
    float4 v1 = *(const float4*)(xr + 4);
    bool lo = (slab == 2);
    uint4 o;
    o.x = pk2(v0.x, v0.y, lo);
    o.y = pk2(v0.z, v0.w, lo);
    o.z = pk2(v1.x, v1.y, lo);
    o.w = pk2(v1.z, v1.w, lo);
    uint32_t ob = (uint32_t)((r << 7) | (g << 4));
    uint32_t so = ob ^ ((ob >> 3) & 0x70);
    char* tile = (char*)(dst + (((size_t)(mt * nchunk + c)) << 13));
    *(uint4*)(tile + so) = o;
}

// weights -> [chunk][512 rows x 64 fp16, SW128-swizzled] (64KB chunks)
// slabs along K': [hi | lo | hi]  (pairs with A's [hi | hi | lo])
__global__ void conv_b_kernel(const float* __restrict__ w, __half* __restrict__ dst,
                              int kshift)
{
    int idx = blockIdx.x * 256 + threadIdx.x;
    int g = idx & 7;
    int n = (idx >> 3) & 511;
    int c = idx >> 12;
    int kk = c * 64 + g * 8;
    int slab = kk >> kshift;
    int k = kk - (slab << kshift);
    const float* wr = w + (((size_t)n) << kshift) + k;
    float4 v0 = *(const float4*)wr;
    float4 v1 = *(const float4*)(wr + 4);
    bool lo = (slab == 1);
    uint4 o;
    o.x = pk2(v0.x, v0.y, lo);
    o.y = pk2(v0.z, v0.w, lo);
    o.z = pk2(v1.x, v1.y, lo);
    o.w = pk2(v1.z, v1.w, lo);
    uint32_t ob = (uint32_t)((n << 7) | (g << 4));
    uint32_t so = ob ^ ((ob >> 3) & 0x70);
    char* chunk = (char*)(dst + (((size_t)c) << 15));
    *(uint4*)(chunk + so) = o;
}

// ---------------- HMMA GEMM: C[128 rows x 256 gates] per CTA ----------------
// K=128 super-chunks (2 logical 64-chunks per stage), 2-stage pipeline.
// Stage = A 32KB (two contiguous 16KB tiles) + B 64KB (two 32KB j-half copies).
// Same inner ldmatrix/mma body as the proven R10 kernel, with tile select ks>>2.
#define GEMM_SMEM 200704
__global__ __launch_bounds__(512, 1) void gemm_hmma_kernel(
    const __half* __restrict__ Ap, const __half* __restrict__ Bp,
    const float* __restrict__ b1, const float* __restrict__ b2,
    float* __restrict__ C, int nsc)
{
    extern __shared__ char smem_raw[];
    uint32_t sb0 = smem_u32(smem_raw);
    uint32_t ab = (sb0 + 1023) & ~1023u;                 // 1024-aligned base
    float* smbias = (float*)(smem_raw + (ab - sb0));     // 512 floats at offset 0

    const int tid = threadIdx.x;
    const int lane = tid & 31, wid = tid >> 5;
    const int wm = wid >> 2, wn = wid & 3;
    const int sub = lane >> 3, l7 = lane & 7;

    if (tid < 512) smbias[tid] = b1[tid] + b2[tid];
    if (tid == 0) {
        mbar_init(ab + 2048, 1); mbar_init(ab + 2056, 1);
    }
    __syncthreads();

    const int mt = blockIdx.x >> 1, j = blockIdx.x & 1;
    const char* Asrc = (const char*)Ap + ((size_t)mt * nsc) * 32768;
    const char* Bsrc = (const char*)Bp + (size_t)j * 32768;

    if (tid == 0) {
        int npre = nsc < 2 ? nsc : 2;
        for (int c = 0; c < npre; c++) {
            uint32_t st = ab + 4096 + c * 98304;
            uint32_t mb = ab + 2048 + c * 8;
            mbar_expect_tx(mb, 98304);
            bulk_g2s(st,         Asrc + (size_t)c * 32768, 32768, mb);
            bulk_g2s(st + 32768, Bsrc + (size_t)(2 * c) * 65536, 32768, mb);
            bulk_g2s(st + 65536, Bsrc + (size_t)(2 * c + 1) * 65536, 32768, mb);
        }
    }

    float acc[2][8][4];
#pragma unroll
    for (int a = 0; a < 2; a++)
#pragma unroll
        for (int b = 0; b < 8; b++)
#pragma unroll
            for (int d = 0; d < 4; d++) acc[a][b][d] = 0.0f;

    const uint32_t xorv = (uint32_t)(l7 << 4);
    const uint32_t arow = (uint32_t)((wm * 32 + (sub & 1) * 8 + l7) * 128);
    const uint32_t akh  = (uint32_t)((sub >> 1) * 16);
    const uint32_t brow = (uint32_t)((wn * 64 + (sub >> 1) * 8 + l7) * 128);
    const uint32_t bkh  = (uint32_t)((sub & 1) * 16);

    for (int c = 0; c < nsc; c++) {
        int s = c & 1;
        uint32_t ph = (uint32_t)((c >> 1) & 1);
        uint32_t mb_full = ab + 2048 + s * 8;
        mbar_wait(mb_full, ph);
        uint32_t Abase = ab + 4096 + s * 98304;
        uint32_t Bbase = Abase + 32768;

#pragma unroll
        for (int ks = 0; ks < 8; ks++) {
            uint32_t At = Abase + (uint32_t)((ks >> 2) * 16384);
            uint32_t Bt = Bbase + (uint32_t)((ks >> 2) * 32768);
            uint32_t kw = (uint32_t)((ks & 3) * 32);
            uint32_t ak = (kw + akh) ^ xorv;
            uint32_t bk = (kw + bkh) ^ xorv;
            uint32_t a0[4], a1[4], bf[4][4];
            ldsm_x4(a0[0], a0[1], a0[2], a0[3], At + arow + ak);
            ldsm_x4(a1[0], a1[1], a1[2], a1[3], At + arow + 2048 + ak);
#pragma unroll
            for (int nb2 = 0; nb2 < 4; nb2++)
                ldsm_x4(bf[nb2][0], bf[nb2][1], bf[nb2][2], bf[nb2][3],
                        Bt + brow + nb2 * 2048 + bk);
#pragma unroll
            for (int nb = 0; nb < 8; nb++) {
                uint32_t bb0 = bf[nb >> 1][(nb & 1) * 2];
                uint32_t bb1 = bf[nb >> 1][(nb & 1) * 2 + 1];
                mma16816(acc[0][nb][0], acc[0][nb][1], acc[0][nb][2], acc[0][nb][3],
                         a0[0], a0[1], a0[2], a0[3], bb0, bb1);
                mma16816(acc[1][nb][0], acc[1][nb][1], acc[1][nb][2], acc[1][nb][3],
                         a1[0], a1[1], a1[2], a1[3], bb0, bb1);
            }
        }
        __syncthreads();
        if (tid == 0 && c + 2 < nsc) {
            int cn = c + 2;
            uint32_t st = ab + 4096 + s * 98304;
            mbar_expect_tx(mb_full, 98304);
            bulk_g2s(st,         Asrc + (size_t)cn * 32768, 32768, mb_full);
            bulk_g2s(st + 32768, Bsrc + (size_t)(2 * cn) * 65536, 32768, mb_full);
            bulk_g2s(st + 65536, Bsrc + (size_t)(2 * cn + 1) * 65536, 32768, mb_full);
        }
    }

    const int mbase = mt * 128 + wm * 32 + (lane >> 2);
    const int colb  = j * 256 + wn * 64 + (lane & 3) * 2;
#pragma unroll
    for (int mb = 0; mb < 2; mb++)
#pragma unroll
        for (int nb = 0; nb < 8; nb++) {
            int cc = colb + nb * 8;
            float bx = smbias[cc], by = smbias[cc + 1];
            size_t r0 = (size_t)(mbase + mb * 16) * GATES + cc;
            float2 v0 = make_float2(acc[mb][nb][0] + bx, acc[mb][nb][1] + by);
            float2 v1 = make_float2(acc[mb][nb][2] + bx, acc[mb][nb][3] + by);
            *(float2*)(C + r0) = v0;
            *(float2*)(C + r0 + (size_t)8 * GATES) = v1;
        }
}

// ---------------- activations ----------------
__device__ __forceinline__ float sigmoidf_(float x) {
    return __fdividef(1.0f, 1.0f + __expf(-x));
}
__device__ __forceinline__ float tanhf_(float x) {
    float a = __expf(2.0f * fabsf(x));
    float r = 1.0f - __fdividef(2.0f, 1.0f + a);
    return copysignf(r, x);
}

// ---------------- LSTM recurrence: R10-exact (256 thr, 2 gates/thr, 96/32 split) ----------------
#define REC_SMEM (8 * 512 * 16 + 128 * 4 + 512 * 4)
__global__ __launch_bounds__(256, 1) void lstm_rec_kernel(
    const float* __restrict__ xg, const float* __restrict__ w_hh,
    float* __restrict__ hout, float* __restrict__ hlast, int T)
{
    extern __shared__ float smem[];
    float4* sw = (float4*)smem;                 // [kc 0..7][row 0..511] float4 (k=96..127)
    float* h_s = smem + 8 * 512 * 4;            // 128 floats
    float* gates = h_s + 128;                   // 512 floats (activated)

    const int tid = threadIdx.x;
    const int b = blockIdx.x;
    const int rowA = tid;                        // i (0..127) / f (128..255): sigmoid
    const int rowB = tid + 256;                  // g (256..383): tanh / o (384..511): sigmoid
    const bool b_is_tanh = (tid < 128);

    const float4* wrowA = (const float4*)(w_hh + (size_t)rowA * HID);
    const float4* wrowB = (const float4*)(w_hh + (size_t)rowB * HID);
    u64b wrA[48], wrB[48];
#pragma unroll
    for (int i = 0; i < 24; i++) {
        float4 va = wrowA[i];
        wrA[2 * i]     = pk64(va.x, va.y);
        wrA[2 * i + 1] = pk64(va.z, va.w);
        float4 vb = wrowB[i];
        wrB[2 * i]     = pk64(vb.x, vb.y);
        wrB[2 * i + 1] = pk64(vb.z, vb.w);
    }
#pragma unroll
    for (int kc = 0; kc < 8; kc++) {
        sw[kc * 512 + rowA] = wrowA[24 + kc];   // k = 96..127
        sw[kc * 512 + rowB] = wrowB[24 + kc];
    }

    if (tid < HID) h_s[tid] = 0.0f;
    float c = 0.0f;
    __syncthreads();

    const float* xg_bA = xg + ((size_t)b * T) * GATES + rowA;
    const float* xg_bB = xg + ((size_t)b * T) * GATES + rowB;
    float xgA = xg_bA[0];
    float xgB = xg_bB[0];

    for (int t = 0; t < T; t++) {
        float xgA_n = (t + 1 < T) ? xg_bA[(size_t)(t + 1) * GATES] : 0.0f;
        float xgB_n = (t + 1 < T) ? xg_bB[(size_t)(t + 1) * GATES] : 0.0f;

        u64b a0 = pk64(xgA, 0.0f), a1 = pk64(0.0f, 0.0f);
        u64b b0 = pk64(xgB, 0.0f), b1 = pk64(0.0f, 0.0f);
        const ulonglong2* h2 = (const ulonglong2*)h_s;
        // k = 0..95: h broadcast + register weights, 4 independent chains
#pragma unroll
        for (int i = 0; i < 24; i++) {
            ulonglong2 hv = h2[i];
            ffma2(a0, hv.x, wrA[2 * i]);
            ffma2(a1, hv.y, wrA[2 * i + 1]);
            ffma2(b0, hv.x, wrB[2 * i]);
            ffma2(b1, hv.y, wrB[2 * i + 1]);
        }
        // k = 96..127: weights from smem
#pragma unroll
        for (int kc = 0; kc < 8; kc++) {
            ulonglong2 hv = h2[24 + kc];
            float4 wa = sw[kc * 512 + rowA];
            ulonglong2 wau = *reinterpret_cast<ulonglong2*>(&wa);
            ffma2(a0, hv.x, wau.x);
            ffma2(a1, hv.y, wau.y);
            float4 wb = sw[kc * 512 + rowB];
            ulonglong2 wbu = *reinterpret_cast<ulonglong2*>(&wb);
            ffma2(b0, hv.x, wbu.x);
            ffma2(b1, hv.y, wbu.y);
        }
        float2 fa0 = upk64(a0), fa1 = upk64(a1);
        float2 fb0 = upk64(b0), fb1 = upk64(b1);
        float preA = (fa0.x + fa0.y) + (fa1.x + fa1.y);
        float preB = (fb0.x + fb0.y) + (fb1.x + fb1.y);
        gates[rowA] = sigmoidf_(preA);                                // i or f
        gates[rowB] = b_is_tanh ? tanhf_(preB) : sigmoidf_(preB);     // g or o
        __syncthreads();

        if (tid < HID) {
            float ig = gates[tid];
            float fg = gates[HID + tid];
            float gg = gates[2 * HID + tid];
            float og = gates[3 * HID + tid];
            c = fg * c + ig * gg;
            float h = og * tanhf_(c);
            h_s[tid] = h;
            if (hout) hout[((size_t)b * T + t) * HID + tid] = h;
        }
        __syncthreads();
        xgA = xgA_n;
        xgB = xgB_n;
    }
    if (hlast && tid < HID) hlast[b * HID + tid] = h_s[tid];
}

// ---------------- final FC ----------------
__global__ void fc_kernel(const float* __restrict__ hlast, const float* __restrict__ fc_w,
                          const float* __restrict__ fc_b, float* __restrict__ out)
{
    int tid = threadIdx.x;
    int b = tid >> 3;
    int cls = tid & 7;
    const float* hv = hlast + b * HID;
    const float* wv = fc_w + cls * HID;
    float s = fc_b[cls];
#pragma unroll 8
    for (int j = 0; j < HID; j++) s += hv[j] * wv[j];
    out[b * NCLS + cls] = s;
}

// ---------------- launch ----------------
extern "C" void kernel_launch(void* const* d_in, const int* in_sizes, int n_in,
                              void* d_out, int out_size)
{
    const float* x     = (const float*)d_in[0];
    const float* w_ih0 = (const float*)d_in[1];
    const float* w_hh0 = (const float*)d_in[2];
    const float* b_ih0 = (const float*)d_in[3];
    const float* b_hh0 = (const float*)d_in[4];
    const float* w_ih1 = (const float*)d_in[5];
    const float* w_hh1 = (const float*)d_in[6];
    const float* b_ih1 = (const float*)d_in[7];
    const float* b_hh1 = (const float*)d_in[8];
    const float* fc_w  = (const float*)d_in[9];
    const float* fc_b  = (const float*)d_in[10];
    float* out = (float*)d_out;

    float *xg_p = nullptr, *h1_p = nullptr, *hl_p = nullptr;
    __half *as_p = nullptr, *bs0_p = nullptr, *bs1_p = nullptr;
    cudaGetSymbolAddress((void**)&xg_p, g_xg);
    cudaGetSymbolAddress((void**)&h1_p, g_h1);
    cudaGetSymbolAddress((void**)&hl_p, g_hlast);
    cudaGetSymbolAddress((void**)&as_p, g_as);
    cudaGetSymbolAddress((void**)&bs0_p, g_bs0);
    cudaGetSymbolAddress((void**)&bs1_p, g_bs1);

    cudaFuncSetAttribute(lstm_rec_kernel,
                         cudaFuncAttributeMaxDynamicSharedMemorySize, REC_SMEM);
    cudaFuncSetAttribute(gemm_hmma_kernel,
                         cudaFuncAttributeMaxDynamicSharedMemorySize, GEMM_SMEM);

    // weight conversions (tiny)
    conv_b_kernel<<<NCH0 * 512 * 8 / 256, 256>>>(w_ih0, bs0_p, 10);
    conv_b_kernel<<<NCH1 * 512 * 8 / 256, 256>>>(w_ih1, bs1_p, 7);

    // layer 0: x -> split-fp16 tiles -> HMMA GEMM (K=128 super-chunks) -> recurrence
    conv_a_kernel<<<MTILES * NCH0 * 1024 / 256, 256>>>(x, as_p, NCH0, 10);
    gemm_hmma_kernel<<<MTILES * 2, 512, GEMM_SMEM>>>(as_p, bs0_p, b_ih0, b_hh0, xg_p, NSC0);
    lstm_rec_kernel<<<BATCH, 256, REC_SMEM>>>(xg_p, w_hh0, h1_p, nullptr, SEQT);

    // layer 1: h1 -> split-fp16 tiles -> HMMA GEMM -> recurrence
    conv_a_kernel<<<MTILES * NCH1 * 1024 / 256, 256>>>(h1_p, as_p, NCH1, 7);
    gemm_hmma_kernel<<<MTILES * 2, 512, GEMM_SMEM>>>(as_p, bs1_p, b_ih1, b_hh1, xg_p, NSC1);
    lstm_rec_kernel<<<BATCH, 256, REC_SMEM>>>(xg_p, w_hh1, nullptr, hl_p, SEQT);

    // FC head
    fc_kernel<<<1, BATCH * NCLS>>>(hl_p, fc_w, fc_b, out);
}